// round 1
// baseline (speedup 1.0000x reference)
#include <cuda_runtime.h>
#include <cstdint>

// BilinearInteraction: out[b, p, :] = x[b, i_p, :] * (x[b, j_p, :] @ W)
//   x: [4096, 32, 64] f32, W: [64, 64] f32, out: [4096, 496, 64] f32
//   pairs (i,j), i<j, row-major triu k=1 ordering.

#define NF 32
#define ED 64
#define NP 496           // NF*(NF-1)/2
#define NTHREADS 256
#define NBATCH 4096

__global__ void __launch_bounds__(NTHREADS, 6)
bilinear_kernel(const float* __restrict__ x,
                const float* __restrict__ W,
                float* __restrict__ out)
{
    __shared__ float xs[NF * ED];      // 8 KB  : x[b] tile
    __shared__ float Ws[ED * ED];      // 16 KB : W
    __shared__ float vs[NF * ED];      // 8 KB  : vid[b] tile
    __shared__ unsigned short pairs[NP];

    const int b   = blockIdx.x;
    const int tid = threadIdx.x;

    // ---- Load x[b] (512 float4) and W (1024 float4) into SMEM ----
    {
        const float4* xg  = (const float4*)(x + (size_t)b * (NF * ED));
        float4*       xs4 = (float4*)xs;
        xs4[tid]       = xg[tid];
        xs4[tid + 256] = xg[tid + 256];

        const float4* wg  = (const float4*)W;
        float4*       ws4 = (float4*)Ws;
#pragma unroll
        for (int k = 0; k < 4; k++)
            ws4[tid + k * 256] = wg[tid + k * 256];
    }

    // ---- Pair table: thread i fills row i's (i,j) entries ----
    if (tid < NF - 1) {
        const int i = tid;
        int s = i * (NF - 1) - (i * (i - 1)) / 2;   // start offset of row i
#pragma unroll 1
        for (int j = i + 1; j < NF; j++)
            pairs[s + (j - i - 1)] = (unsigned short)((i << 8) | j);
    }
    __syncthreads();

    // ---- Compute vid[f][e] = sum_d x[f][d] * W[d][e] ----
    // Thread owns column e = tid & 63 and 8 rows f = fb + 4*k (fb = tid>>6).
    // Within a warp fb is constant -> x loads are uniform (SMEM broadcast);
    // W loads are consecutive in e -> conflict-free.
    {
        const int e  = tid & 63;
        const int fb = tid >> 6;

        float acc[8];
#pragma unroll
        for (int k = 0; k < 8; k++) acc[k] = 0.0f;

        const float4* xs4 = (const float4*)xs;
#pragma unroll
        for (int d4 = 0; d4 < ED; d4 += 4) {
            const float w0 = Ws[(d4 + 0) * ED + e];
            const float w1 = Ws[(d4 + 1) * ED + e];
            const float w2 = Ws[(d4 + 2) * ED + e];
            const float w3 = Ws[(d4 + 3) * ED + e];
#pragma unroll
            for (int k = 0; k < 8; k++) {
                const int f = fb + 4 * k;
                const float4 xv = xs4[f * (ED / 4) + (d4 >> 2)];
                acc[k] = fmaf(xv.x, w0, acc[k]);
                acc[k] = fmaf(xv.y, w1, acc[k]);
                acc[k] = fmaf(xv.z, w2, acc[k]);
                acc[k] = fmaf(xv.w, w3, acc[k]);
            }
        }
#pragma unroll
        for (int k = 0; k < 8; k++)
            vs[(fb + 4 * k) * ED + e] = acc[k];
    }
    __syncthreads();

    // ---- Write phase: 496 pairs * 16 float4 = 7936 float4 / 256 thr = 31 each ----
    {
        float4*       out4 = (float4*)(out + (size_t)b * (NP * ED));
        const float4* xs4  = (const float4*)xs;
        const float4* vs4  = (const float4*)vs;

#pragma unroll
        for (int it = 0; it < 31; it++) {
            const int idx = tid + it * NTHREADS;   // 0..7935
            const int p   = idx >> 4;
            const int v   = idx & 15;
            const unsigned int pr = pairs[p];
            const int i = pr >> 8;
            const int j = pr & 255;
            const float4 a = xs4[i * (ED / 4) + v];
            const float4 c = vs4[j * (ED / 4) + v];
            float4 r;
            r.x = a.x * c.x;
            r.y = a.y * c.y;
            r.z = a.z * c.z;
            r.w = a.w * c.w;
            out4[idx] = r;
        }
    }
}

extern "C" void kernel_launch(void* const* d_in, const int* in_sizes, int n_in,
                              void* d_out, int out_size)
{
    const float* x = (const float*)d_in[0];
    const float* W = (const float*)d_in[1];
    float*       o = (float*)d_out;
    bilinear_kernel<<<NBATCH, NTHREADS>>>(x, W, o);
}

// round 2
// speedup vs baseline: 1.1579x; 1.1579x over previous
#include <cuda_runtime.h>
#include <cstdint>

// BilinearInteraction: out[b, p, :] = x[b, i_p, :] * (x[b, j_p, :] @ W)
//   x: [4096, 32, 64] f32, W: [64, 64] f32, out: [4096, 496, 64] f32
//   pairs (i,j), i<j, row-major triu k=1 ordering.

#define NF 32
#define ED 64
#define NP 496           // NF*(NF-1)/2
#define NTHREADS 256
#define NBATCH 4096

__global__ void __launch_bounds__(NTHREADS, 6)
bilinear_kernel(const float* __restrict__ x,
                const float* __restrict__ W,
                float* __restrict__ out)
{
    __shared__ float xs[NF * ED];      // 8 KB  : x[b] tile
    __shared__ float Ws[ED * ED];      // 16 KB : W
    __shared__ float vs[NF * ED];      // 8 KB  : vid[b] tile

    const int b   = blockIdx.x;
    const int tid = threadIdx.x;

    // ---- Load x[b] (512 float4) and W (1024 float4) into SMEM ----
    {
        const float4* xg  = (const float4*)(x + (size_t)b * (NF * ED));
        float4*       xs4 = (float4*)xs;
        xs4[tid]       = xg[tid];
        xs4[tid + 256] = xg[tid + 256];

        const float4* wg  = (const float4*)W;
        float4*       ws4 = (float4*)Ws;
#pragma unroll
        for (int k = 0; k < 4; k++)
            ws4[tid + k * 256] = wg[tid + k * 256];
    }
    __syncthreads();

    // ---- Compute vid[f][e] = sum_d x[f][d] * W[d][e] ----
    // Thread owns column e = tid & 63 and 8 strided rows f = fb + 4*k.
    {
        const int e  = tid & 63;
        const int fb = tid >> 6;

        float acc[8];
#pragma unroll
        for (int k = 0; k < 8; k++) acc[k] = 0.0f;

        const float4* xs4 = (const float4*)xs;
#pragma unroll
        for (int d4 = 0; d4 < ED; d4 += 4) {
            const float w0 = Ws[(d4 + 0) * ED + e];
            const float w1 = Ws[(d4 + 1) * ED + e];
            const float w2 = Ws[(d4 + 2) * ED + e];
            const float w3 = Ws[(d4 + 3) * ED + e];
#pragma unroll
            for (int k = 0; k < 8; k++) {
                const int f = fb + 4 * k;
                const float4 xv = xs4[f * (ED / 4) + (d4 >> 2)];
                acc[k] = fmaf(xv.x, w0, acc[k]);
                acc[k] = fmaf(xv.y, w1, acc[k]);
                acc[k] = fmaf(xv.z, w2, acc[k]);
                acc[k] = fmaf(xv.w, w3, acc[k]);
            }
        }
#pragma unroll
        for (int k = 0; k < 8; k++)
            vs[(fb + 4 * k) * ED + e] = acc[k];
    }
    __syncthreads();

    // ---- Write phase: row-grouped pairs, x[i] cached in a register ----
    // Warp w handles rows {w, 30-w, 15-w, 15+w} (warp 0: {0, 30, 15}).
    // Lane: v = lane&15 (float4 column), h = lane>>4 selects j vs j+1.
    // Per iteration: 1 LDS.128 (vid[j..j+1], 512B) + 1 STG.128 (contiguous
    // 512B, pairs p and p+1) -> 8 L1 wavefronts / 512B output.
    {
        const int w    = tid >> 5;
        const int lane = tid & 31;
        const int v    = lane & 15;
        const int h    = lane >> 4;

        float4*       out4 = (float4*)(out + (size_t)b * (NP * ED));
        const float4* xs4  = (const float4*)xs;
        const float4* vs4  = (const float4*)vs;

        int rows[4];
        int nrows;
        if (w == 0) {
            rows[0] = 0; rows[1] = 30; rows[2] = 15; rows[3] = 0;
            nrows = 3;
        } else {
            rows[0] = w; rows[1] = 30 - w; rows[2] = 15 - w; rows[3] = 15 + w;
            nrows = 4;
        }

#pragma unroll
        for (int r = 0; r < 4; r++) {
            if (r >= nrows) break;
            const int i = rows[r];
            const float4 a = xs4[i * (ED / 4) + v];   // x[i] cached in regs
            const int cnt   = 31 - i;                 // pairs in this row
            const int iters = (cnt + 1) >> 1;
            const int p0    = (i * (63 - i)) >> 1;    // row start in pair index

#pragma unroll 2
            for (int t = 0; t < iters; t++) {
                const int j = i + 1 + 2 * t + h;
                if (j < NF) {
                    const float4 c = vs4[j * (ED / 4) + v];
                    const int p = p0 + (j - i - 1);
                    float4 rr;
                    rr.x = a.x * c.x;
                    rr.y = a.y * c.y;
                    rr.z = a.z * c.z;
                    rr.w = a.w * c.w;
                    out4[p * (ED / 4) + v] = rr;
                }
            }
        }
    }
}

extern "C" void kernel_launch(void* const* d_in, const int* in_sizes, int n_in,
                              void* d_out, int out_size)
{
    const float* x = (const float*)d_in[0];
    const float* W = (const float*)d_in[1];
    float*       o = (float*)d_out;
    bilinear_kernel<<<NBATCH, NTHREADS>>>(x, W, o);
}